// round 6
// baseline (speedup 1.0000x reference)
#include <cuda_runtime.h>
#include <cuda_bf16.h>

// Problem constants (fixed by the reference)
#define NN 50000
#define EE 800000
#define HH 64
#define EDD 32
#define LL 3
#define GG 256
#define OUTD 32
#define EDGE_CAT 10
#define SCALE 0.125f  // 1/sqrt(64)

// ---------------- scratch (device globals; no allocation allowed) -----------
__device__ float d_h[NN * HH];
__device__ float d_q[NN * HH];
__device__ float d_k[NN * HH];
__device__ float d_v[NN * HH];
__device__ float d_s[NN * HH];      // skip projection h@Wskip + bskip
__device__ float d_ecat[LL * EDGE_CAT * HH];
__device__ float d_gate[NN];
__device__ unsigned d_gmax[GG];
__device__ float d_gdenom[GG];
// CSR scratch
__device__ int d_deg[NN];
__device__ int d_rowptr[NN + 1];
__device__ int d_wp[NN];
__device__ int d_csr[EE];           // packed: src | (cat<<16)
__device__ int d_bsum[64];
__device__ int d_bpre[65];

// order-preserving float<->uint encoding for atomicMax on floats
#define ENC_NEG_INF 0x007fffffu
__device__ __forceinline__ unsigned enc_f(float f) {
    unsigned b = __float_as_uint(f);
    return (b & 0x80000000u) ? ~b : (b | 0x80000000u);
}
__device__ __forceinline__ float dec_f(unsigned u) {
    unsigned b = (u & 0x80000000u) ? (u & 0x7fffffffu) : ~u;
    return __uint_as_float(b);
}

// ---------------- CSR build --------------------------------------------------

__global__ void hist_init_kernel() {
    int i = blockIdx.x * blockDim.x + threadIdx.x;
    if (i < NN) d_deg[i] = 0;
}

__global__ void hist_kernel(const int* __restrict__ dst) {
    int e = blockIdx.x * blockDim.x + threadIdx.x;
    if (e < EE) atomicAdd(&d_deg[dst[e]], 1);
}

// block-local exclusive scan; block totals to d_bsum
__global__ void scan_blocks_kernel() {
    __shared__ int wsum[32];
    int t = threadIdx.x, lane = t & 31, w = t >> 5;
    int i = blockIdx.x * 1024 + t;
    int v = (i < NN) ? d_deg[i] : 0;
    int x = v;
#pragma unroll
    for (int o = 1; o < 32; o <<= 1) {
        int y = __shfl_up_sync(0xffffffffu, x, o);
        if (lane >= o) x += y;
    }
    if (lane == 31) wsum[w] = x;
    __syncthreads();
    if (w == 0) {
        int ws = wsum[lane];
#pragma unroll
        for (int o = 1; o < 32; o <<= 1) {
            int y = __shfl_up_sync(0xffffffffu, ws, o);
            if (lane >= o) ws += y;
        }
        wsum[lane] = ws;
    }
    __syncthreads();
    int incl = x + (w > 0 ? wsum[w - 1] : 0);
    if (i < NN) d_rowptr[i] = incl - v;
    if (t == 1023) d_bsum[blockIdx.x] = incl;
}

// scan the block totals (1 block of 64 threads)
__global__ void scan_tops_kernel() {
    __shared__ int tmp[64];
    int t = threadIdx.x;
    int nb = (NN + 1023) / 1024;
    tmp[t] = (t < nb) ? d_bsum[t] : 0;
    __syncthreads();
    for (int o = 1; o < 64; o <<= 1) {
        int a = (t >= o) ? tmp[t - o] : 0;
        __syncthreads();
        tmp[t] += a;
        __syncthreads();
    }
    d_bpre[t + 1] = tmp[t];
    if (t == 0) d_bpre[0] = 0;
}

__global__ void scan_add_kernel() {
    int i = blockIdx.x * blockDim.x + threadIdx.x;
    if (i < NN) {
        int r = d_rowptr[i] + d_bpre[i >> 10];
        d_rowptr[i] = r;
        d_wp[i] = r;
    } else if (i == NN) {
        d_rowptr[NN] = d_bpre[(NN + 1023) >> 10];
    }
}

__global__ void scatter_kernel(const int* __restrict__ src,
                               const int* __restrict__ dst,
                               const int* __restrict__ ea) {
    int e = blockIdx.x * blockDim.x + threadIdx.x;
    if (e >= EE) return;
    int d = dst[e];
    int pos = atomicAdd(&d_wp[d], 1);
    d_csr[pos] = src[e] | (ea[e] << 16);
}

// ---------------- misc small kernels -----------------------------------------

// e_cat[l][cat][j] = sum_c edge_emb[cat][c] * We[l][c][j]   for all layers
__global__ void ecat_kernel(const float* __restrict__ edge_emb,
                            const float* __restrict__ We) {
    int l = blockIdx.x / EDGE_CAT;
    int cat = blockIdx.x % EDGE_CAT;
    int j = threadIdx.x;
    const float* W = We + (size_t)l * EDD * HH;
    float acc = 0.f;
#pragma unroll
    for (int c = 0; c < EDD; c++)
        acc += edge_emb[cat * EDD + c] * W[c * HH + j];
    d_ecat[(l * EDGE_CAT + cat) * HH + j] = acc;
}

// ---------------- register-tiled projection GEMM ------------------------------
// One 64x64 weight matrix per blockIdx.y (0:q 1:k 2:v 3:skip).
// BM=128 nodes, BK=64 (full). 256 threads, 8x4 register tile each.
__global__ void __launch_bounds__(256, 2)
proj_gemm(const float* __restrict__ Wq, const float* __restrict__ Wk,
          const float* __restrict__ Wv, const float* __restrict__ Ws,
          const float* __restrict__ bq, const float* __restrict__ bk,
          const float* __restrict__ bv, const float* __restrict__ bs,
          const int* __restrict__ x, const float* __restrict__ node_emb,
          int layer0) {
    __shared__ float hs_t[64 * 128];
    __shared__ float ws[64 * 64];

    const float* W;
    const float* bias;
    float* out;
    switch (blockIdx.y) {
        case 0:  W = Wq; bias = bq; out = d_q; break;
        case 1:  W = Wk; bias = bk; out = d_k; break;
        case 2:  W = Wv; bias = bv; out = d_v; break;
        default: W = Ws; bias = bs; out = d_s; break;
    }

    int t = threadIdx.x;
    int nodeBase = blockIdx.x * 128;

    {
        int n = t >> 1;
        int half = (t & 1) * 8;
        int gn = nodeBase + n;
        const float* hrow = nullptr;
        if (gn < NN)
            hrow = layer0 ? (node_emb + (size_t)x[gn] * HH)
                          : (d_h + (size_t)gn * HH);
#pragma unroll
        for (int i = 0; i < 8; i++) {
            int c4 = half + i;
            float4 hv = make_float4(0.f, 0.f, 0.f, 0.f);
            if (hrow) hv = *(const float4*)(hrow + c4 * 4);
            int c = c4 * 4;
            hs_t[(c + 0) * 128 + n] = hv.x;
            hs_t[(c + 1) * 128 + n] = hv.y;
            hs_t[(c + 2) * 128 + n] = hv.z;
            hs_t[(c + 3) * 128 + n] = hv.w;
        }
    }
#pragma unroll
    for (int i = 0; i < 4; i++) {
        int fidx = t * 4 + i;
        *(float4*)(ws + fidx * 4) = *(const float4*)(W + fidx * 4);
    }
    __syncthreads();

    int tx = t >> 4;
    int ty = t & 15;
    float acc[8][4];
#pragma unroll
    for (int u = 0; u < 8; u++)
#pragma unroll
        for (int w = 0; w < 4; w++) acc[u][w] = 0.f;

#pragma unroll 4
    for (int c = 0; c < 64; c++) {
        float4 a0 = *(const float4*)(hs_t + c * 128 + tx * 8);
        float4 a1 = *(const float4*)(hs_t + c * 128 + tx * 8 + 4);
        float4 b  = *(const float4*)(ws + c * 64 + ty * 4);
        float a[8] = {a0.x, a0.y, a0.z, a0.w, a1.x, a1.y, a1.z, a1.w};
        float bv4[4] = {b.x, b.y, b.z, b.w};
#pragma unroll
        for (int u = 0; u < 8; u++)
#pragma unroll
            for (int w = 0; w < 4; w++)
                acc[u][w] += a[u] * bv4[w];
    }

    float4 bb = *(const float4*)(bias + ty * 4);
#pragma unroll
    for (int u = 0; u < 8; u++) {
        int n = nodeBase + tx * 8 + u;
        if (n < NN) {
            float4 o = make_float4(acc[u][0] + bb.x, acc[u][1] + bb.y,
                                   acc[u][2] + bb.z, acc[u][3] + bb.w);
            *(float4*)(out + (size_t)n * HH + ty * 4) = o;
        }
    }
}

// ---------------- fused flash-style attention layer ---------------------------
// one warp per dst node; 4 edge-groups of 8 lanes; all shuffle loops run a
// UNIFORM trip count across the warp (invalid iterations predicated to w=0).
__global__ void __launch_bounds__(256) attn_kernel(
        int layer, int do_gate,
        const float* __restrict__ gate_W, const float* __restrict__ gate_b,
        const int* __restrict__ batch) {
    __shared__ float ec_s[EDGE_CAT * HH];
    __shared__ float qe_s[8][16];
    const float* ec = d_ecat + layer * EDGE_CAT * HH;
    for (int i = threadIdx.x; i < EDGE_CAT * HH; i += 256)
        ec_s[i] = ec[i];
    __syncthreads();

    int wl = threadIdx.x >> 5;
    int n = blockIdx.x * 8 + wl;
    if (n >= NN) return;     // whole warp exits together; no block syncs below
    int lane = threadIdx.x & 31;
    int g = lane >> 3;     // edge group 0..3
    int fl = lane & 7;     // feature slice (8 floats)

    const float* qr = d_q + (size_t)n * HH + fl * 8;
    float4 q0 = *(const float4*)qr;
    float4 q1 = *(const float4*)(qr + 4);

    // qe[cat] = q . ecat[cat]; 3 uniform iterations covering cats g, g+4, g+8
#pragma unroll
    for (int i = 0; i < 3; i++) {
        int cat = g + i * 4;
        bool valid = (cat < EDGE_CAT);
        int catc = valid ? cat : 0;
        const float* er = ec_s + catc * HH + fl * 8;
        float4 e0 = *(const float4*)er, e1 = *(const float4*)(er + 4);
        float p = q0.x * e0.x + q0.y * e0.y + q0.z * e0.z + q0.w * e0.w +
                  q1.x * e1.x + q1.y * e1.y + q1.z * e1.z + q1.w * e1.w;
        p += __shfl_xor_sync(0xffffffffu, p, 1);
        p += __shfl_xor_sync(0xffffffffu, p, 2);
        p += __shfl_xor_sync(0xffffffffu, p, 4);
        if (valid && fl == 0) qe_s[wl][cat] = p;
    }
    __syncwarp();

    int beg = d_rowptr[n], end = d_rowptr[n + 1];
    int nIter = (end - beg + 3) >> 2;
    float m = -1e30f, ssum = 0.f;
    float4 acc0 = make_float4(0.f, 0.f, 0.f, 0.f);
    float4 acc1 = make_float4(0.f, 0.f, 0.f, 0.f);

    for (int it = 0; it < nIter; it++) {
        int p = beg + it * 4 + g;
        bool valid = (p < end);
        int pc = valid ? p : beg;          // nIter>0 implies beg<end
        int packed = d_csr[pc];
        int s = packed & 0xffff;
        int cat = packed >> 16;
        const float* kr = d_k + (size_t)s * HH + fl * 8;
        const float* vr = d_v + (size_t)s * HH + fl * 8;
        float4 k0 = *(const float4*)kr, k1 = *(const float4*)(kr + 4);
        float4 v0 = *(const float4*)vr, v1 = *(const float4*)(vr + 4);
        float dp = q0.x * k0.x + q0.y * k0.y + q0.z * k0.z + q0.w * k0.w +
                   q1.x * k1.x + q1.y * k1.y + q1.z * k1.z + q1.w * k1.w;
        dp += __shfl_xor_sync(0xffffffffu, dp, 1);
        dp += __shfl_xor_sync(0xffffffffu, dp, 2);
        dp += __shfl_xor_sync(0xffffffffu, dp, 4);
        // alpha uniform within the 8-lane group; -1e30 for invalid slots
        float alpha = valid ? (dp + qe_s[wl][cat]) * SCALE : -1e30f;
        float w;
        if (alpha > m) {       // group-uniform branch
            float c = __expf(m - alpha);
            ssum *= c;
            acc0.x *= c; acc0.y *= c; acc0.z *= c; acc0.w *= c;
            acc1.x *= c; acc1.y *= c; acc1.z *= c; acc1.w *= c;
            m = alpha;
            w = 1.f;
        } else {
            w = __expf(alpha - m);
        }
        if (!valid) w = 0.f;
        ssum += w;
        const float* er = ec_s + cat * HH + fl * 8;
        float4 e0 = *(const float4*)er, e1 = *(const float4*)(er + 4);
        acc0.x += w * (v0.x + e0.x);
        acc0.y += w * (v0.y + e0.y);
        acc0.z += w * (v0.z + e0.z);
        acc0.w += w * (v0.w + e0.w);
        acc1.x += w * (v1.x + e1.x);
        acc1.y += w * (v1.y + e1.y);
        acc1.z += w * (v1.z + e1.z);
        acc1.w += w * (v1.w + e1.w);
    }

    // merge the 4 groups (lanes at stride 8 hold the same feature slice);
    // after this every lane holds the fully merged state
#pragma unroll
    for (int o = 8; o <= 16; o <<= 1) {
        float mo = __shfl_xor_sync(0xffffffffu, m, o);
        float so = __shfl_xor_sync(0xffffffffu, ssum, o);
        float mn = fmaxf(m, mo);
        float cs = __expf(m - mn), co = __expf(mo - mn);
        ssum = ssum * cs + so * co;
        acc0.x = acc0.x * cs + __shfl_xor_sync(0xffffffffu, acc0.x, o) * co;
        acc0.y = acc0.y * cs + __shfl_xor_sync(0xffffffffu, acc0.y, o) * co;
        acc0.z = acc0.z * cs + __shfl_xor_sync(0xffffffffu, acc0.z, o) * co;
        acc0.w = acc0.w * cs + __shfl_xor_sync(0xffffffffu, acc0.w, o) * co;
        acc1.x = acc1.x * cs + __shfl_xor_sync(0xffffffffu, acc1.x, o) * co;
        acc1.y = acc1.y * cs + __shfl_xor_sync(0xffffffffu, acc1.y, o) * co;
        acc1.z = acc1.z * cs + __shfl_xor_sync(0xffffffffu, acc1.z, o) * co;
        acc1.w = acc1.w * cs + __shfl_xor_sync(0xffffffffu, acc1.w, o) * co;
        m = mn;
    }

    float inv = (ssum > 0.f) ? (1.f / ssum) : 0.f;
    // all lanes compute h (identical across groups); only group 0 stores
    const float* sr = d_s + (size_t)n * HH + fl * 8;
    float4 s0 = *(const float4*)sr, s1 = *(const float4*)(sr + 4);
    float4 h0, h1;
    h0.x = fmaxf(acc0.x * inv + s0.x, 0.f);
    h0.y = fmaxf(acc0.y * inv + s0.y, 0.f);
    h0.z = fmaxf(acc0.z * inv + s0.z, 0.f);
    h0.w = fmaxf(acc0.w * inv + s0.w, 0.f);
    h1.x = fmaxf(acc1.x * inv + s1.x, 0.f);
    h1.y = fmaxf(acc1.y * inv + s1.y, 0.f);
    h1.z = fmaxf(acc1.z * inv + s1.z, 0.f);
    h1.w = fmaxf(acc1.w * inv + s1.w, 0.f);
    if (g == 0) {
        *(float4*)(d_h + (size_t)n * HH + fl * 8) = h0;
        *(float4*)(d_h + (size_t)n * HH + fl * 8 + 4) = h1;
    }
    if (do_gate) {
        // every lane participates in the shuffles (uniform)
        const float* gw = gate_W + fl * 8;
        float4 w0 = *(const float4*)gw, w1 = *(const float4*)(gw + 4);
        float gp = h0.x * w0.x + h0.y * w0.y + h0.z * w0.z + h0.w * w0.w +
                   h1.x * w1.x + h1.y * w1.y + h1.z * w1.z + h1.w * w1.w;
        gp += __shfl_xor_sync(0xffffffffu, gp, 1);
        gp += __shfl_xor_sync(0xffffffffu, gp, 2);
        gp += __shfl_xor_sync(0xffffffffu, gp, 4);
        if (lane == 0) {
            float gv = gp + gate_b[0];
            d_gate[n] = gv;
            atomicMax(&d_gmax[batch[n]], enc_f(gv));
        }
    }
}

// ---------------- readout -----------------------------------------------------

__global__ void readout_init_kernel(float* __restrict__ out) {
    int i = blockIdx.x * blockDim.x + threadIdx.x;
    if (i < GG * OUTD) out[i] = 0.f;
    if (i < GG) {
        d_gmax[i] = ENC_NEG_INF;
        d_gdenom[i] = 0.f;
    }
}

__global__ void gexp_kernel(const int* __restrict__ batch) {
    int n = blockIdx.x * blockDim.x + threadIdx.x;
    if (n >= NN) return;
    int b = batch[n];
    float g = __expf(d_gate[n] - dec_f(d_gmax[b]));
    d_gate[n] = g;
    atomicAdd(&d_gdenom[b], g);
}

// out[batch[n]] += (gate/denom) * (h[n] @ out_W + out_b); 8 nodes/block
__global__ void out_kernel(const int* __restrict__ batch,
                           const float* __restrict__ out_W,
                           const float* __restrict__ out_b,
                           float* __restrict__ out) {
    __shared__ float ow[HH * OUTD];   // 8KB
    __shared__ float hs[8][HH];
    int t = threadIdx.x;
    for (int i = t; i < HH * OUTD; i += 256) ow[i] = out_W[i];
    for (int i = t; i < 8 * HH; i += 256) {
        int r = i >> 6, c = i & 63;
        int n2 = blockIdx.x * 8 + r;
        hs[r][c] = (n2 < NN) ? d_h[n2 * HH + c] : 0.f;
    }
    __syncthreads();
    int j = t & 31, g = t >> 5;
    int n = blockIdx.x * 8 + g;
    if (n >= NN) return;
    float acc = out_b[j];
#pragma unroll
    for (int c = 0; c < HH; c++) acc += hs[g][c] * ow[c * OUTD + j];
    int b = batch[n];
    float w = d_gate[n] / d_gdenom[b];
    atomicAdd(&out[b * OUTD + j], w * acc);
}

// ---------------- launch -----------------------------------------------------

extern "C" void kernel_launch(void* const* d_in, const int* in_sizes, int n_in,
                              void* d_out, int out_size) {
    const int* x          = (const int*)d_in[0];
    const int* edge_index = (const int*)d_in[1];
    const int* src        = edge_index;
    const int* dst        = edge_index + EE;
    const int* ea         = (const int*)d_in[2];
    const int* batch      = (const int*)d_in[3];
    const float* node_emb = (const float*)d_in[4];
    const float* edge_emb = (const float*)d_in[5];
    const float* Wq       = (const float*)d_in[6];
    const float* Wk       = (const float*)d_in[7];
    const float* Wv       = (const float*)d_in[8];
    const float* We       = (const float*)d_in[9];
    const float* Wskip    = (const float*)d_in[10];
    const float* bq       = (const float*)d_in[11];
    const float* bk       = (const float*)d_in[12];
    const float* bv       = (const float*)d_in[13];
    const float* bskip    = (const float*)d_in[14];
    const float* gate_W   = (const float*)d_in[15];
    const float* gate_b   = (const float*)d_in[16];
    const float* out_W    = (const float*)d_in[17];
    const float* out_b    = (const float*)d_in[18];
    float* out            = (float*)d_out;

    const int E_BLOCKS  = (EE + 255) / 256;
    const int N_BLOCKS  = (NN + 255) / 256;
    const int SCAN_BLOCKS = (NN + 1023) / 1024;

    // CSR build (by dst)
    hist_init_kernel<<<N_BLOCKS, 256>>>();
    hist_kernel<<<E_BLOCKS, 256>>>(dst);
    scan_blocks_kernel<<<SCAN_BLOCKS, 1024>>>();
    scan_tops_kernel<<<1, 64>>>();
    scan_add_kernel<<<(NN + 1 + 1023) / 1024, 1024>>>();
    scatter_kernel<<<E_BLOCKS, 256>>>(src, dst, ea);

    ecat_kernel<<<LL * EDGE_CAT, HH>>>(edge_emb, We);

    dim3 gemm_grid((NN + 127) / 128, 4);
    const int ATTN_BLOCKS = (NN + 7) / 8;
    for (int l = 0; l < LL; l++) {
        if (l == LL - 1)
            readout_init_kernel<<<(GG * OUTD + 255) / 256, 256>>>(out);
        proj_gemm<<<gemm_grid, 256>>>(
            Wq + (size_t)l * HH * HH, Wk + (size_t)l * HH * HH,
            Wv + (size_t)l * HH * HH, Wskip + (size_t)l * HH * HH,
            bq + (size_t)l * HH, bk + (size_t)l * HH,
            bv + (size_t)l * HH, bskip + (size_t)l * HH,
            x, node_emb, (l == 0) ? 1 : 0);
        attn_kernel<<<ATTN_BLOCKS, 256>>>(l, (l == LL - 1) ? 1 : 0,
                                          gate_W, gate_b, batch);
    }

    gexp_kernel<<<N_BLOCKS, 256>>>(batch);
    out_kernel<<<(NN + 7) / 8, 256>>>(batch, out_W, out_b, out);
}

// round 10
// speedup vs baseline: 1.1191x; 1.1191x over previous
#include <cuda_runtime.h>
#include <cuda_bf16.h>
#include <cuda_fp16.h>

// Problem constants (fixed by the reference)
#define NN 50000
#define EE 800000
#define HH 64
#define EDD 32
#define LL 3
#define GG 256
#define OUTD 32
#define EDGE_CAT 10
#define SCALE 0.125f  // 1/sqrt(64)

// ---------------- scratch (device globals; no allocation allowed) -----------
__device__ float d_h[NN * HH];
__device__ float d_q[NN * HH];
__device__ float d_s[NN * HH];        // skip projection h@Wskip + bskip
__device__ __half2 d_k16[NN * 32];    // fp16 keys   (64 halves per node)
__device__ __half2 d_v16[NN * 32];    // fp16 values
__device__ float d_ecat[LL * EDGE_CAT * HH];
__device__ float d_gate[NN];
__device__ unsigned d_gmax[GG];
__device__ float d_gdenom[GG];
// CSR scratch
__device__ int d_deg[NN];
__device__ int d_rowptr[NN + 1];
__device__ int d_wp[NN];
__device__ int d_csr[EE];             // packed: src | (cat<<16)
__device__ int d_bsum[64];
__device__ int d_bpre[65];

// order-preserving float<->uint encoding for atomicMax on floats
#define ENC_NEG_INF 0x007fffffu
__device__ __forceinline__ unsigned enc_f(float f) {
    unsigned b = __float_as_uint(f);
    return (b & 0x80000000u) ? ~b : (b | 0x80000000u);
}
__device__ __forceinline__ float dec_f(unsigned u) {
    unsigned b = (u & 0x80000000u) ? (u & 0x7fffffffu) : ~u;
    return __uint_as_float(b);
}

// ---------------- CSR build --------------------------------------------------

__global__ void hist_init_kernel() {
    int i = blockIdx.x * blockDim.x + threadIdx.x;
    if (i < NN) d_deg[i] = 0;
}

__global__ void hist_kernel(const int* __restrict__ dst) {
    int e = blockIdx.x * blockDim.x + threadIdx.x;
    if (e < EE) atomicAdd(&d_deg[dst[e]], 1);
}

// block-local exclusive scan; block totals to d_bsum
__global__ void scan_blocks_kernel() {
    __shared__ int wsum[32];
    int t = threadIdx.x, lane = t & 31, w = t >> 5;
    int i = blockIdx.x * 1024 + t;
    int v = (i < NN) ? d_deg[i] : 0;
    int x = v;
#pragma unroll
    for (int o = 1; o < 32; o <<= 1) {
        int y = __shfl_up_sync(0xffffffffu, x, o);
        if (lane >= o) x += y;
    }
    if (lane == 31) wsum[w] = x;
    __syncthreads();
    if (w == 0) {
        int ws = wsum[lane];
#pragma unroll
        for (int o = 1; o < 32; o <<= 1) {
            int y = __shfl_up_sync(0xffffffffu, ws, o);
            if (lane >= o) ws += y;
        }
        wsum[lane] = ws;
    }
    __syncthreads();
    int incl = x + (w > 0 ? wsum[w - 1] : 0);
    if (i < NN) d_rowptr[i] = incl - v;
    if (t == 1023) d_bsum[blockIdx.x] = incl;
}

// scan the block totals (1 block of 64 threads)
__global__ void scan_tops_kernel() {
    __shared__ int tmp[64];
    int t = threadIdx.x;
    int nb = (NN + 1023) / 1024;
    tmp[t] = (t < nb) ? d_bsum[t] : 0;
    __syncthreads();
    for (int o = 1; o < 64; o <<= 1) {
        int a = (t >= o) ? tmp[t - o] : 0;
        __syncthreads();
        tmp[t] += a;
        __syncthreads();
    }
    d_bpre[t + 1] = tmp[t];
    if (t == 0) d_bpre[0] = 0;
}

__global__ void scan_add_kernel() {
    int i = blockIdx.x * blockDim.x + threadIdx.x;
    if (i < NN) {
        int r = d_rowptr[i] + d_bpre[i >> 10];
        d_rowptr[i] = r;
        d_wp[i] = r;
    } else if (i == NN) {
        d_rowptr[NN] = d_bpre[(NN + 1023) >> 10];
    }
}

__global__ void scatter_kernel(const int* __restrict__ src,
                               const int* __restrict__ dst,
                               const int* __restrict__ ea) {
    int e = blockIdx.x * blockDim.x + threadIdx.x;
    if (e >= EE) return;
    int d = dst[e];
    int pos = atomicAdd(&d_wp[d], 1);
    d_csr[pos] = src[e] | (ea[e] << 16);
}

// ---------------- misc small kernels -----------------------------------------

// e_cat[l][cat][j] = sum_c edge_emb[cat][c] * We[l][c][j]   for all layers
__global__ void ecat_kernel(const float* __restrict__ edge_emb,
                            const float* __restrict__ We) {
    int l = blockIdx.x / EDGE_CAT;
    int cat = blockIdx.x % EDGE_CAT;
    int j = threadIdx.x;
    const float* W = We + (size_t)l * EDD * HH;
    float acc = 0.f;
#pragma unroll
    for (int c = 0; c < EDD; c++)
        acc += edge_emb[cat * EDD + c] * W[c * HH + j];
    d_ecat[(l * EDGE_CAT + cat) * HH + j] = acc;
}

// ---------------- register-tiled projection GEMM ------------------------------
// blockIdx.y: 0=q(fp32) 1=skip(fp32) 2=k(fp16) 3=v(fp16)
// BM=128 nodes, BK=64 (full). 256 threads, 8x4 register tile each.
__global__ void __launch_bounds__(256, 2)
proj_gemm(const float* __restrict__ Wq, const float* __restrict__ Wk,
          const float* __restrict__ Wv, const float* __restrict__ Ws,
          const float* __restrict__ bq, const float* __restrict__ bk,
          const float* __restrict__ bv, const float* __restrict__ bs,
          const int* __restrict__ x, const float* __restrict__ node_emb,
          int layer0) {
    __shared__ float hs_t[64 * 128];
    __shared__ float ws[64 * 64];

    const float* W;
    const float* bias;
    float* outF = nullptr;
    __half2* outH = nullptr;
    switch (blockIdx.y) {
        case 0:  W = Wq; bias = bq; outF = d_q;   break;
        case 1:  W = Ws; bias = bs; outF = d_s;   break;
        case 2:  W = Wk; bias = bk; outH = d_k16; break;
        default: W = Wv; bias = bv; outH = d_v16; break;
    }

    int t = threadIdx.x;
    int nodeBase = blockIdx.x * 128;

    {
        int n = t >> 1;
        int hoff = (t & 1) * 8;
        int gn = nodeBase + n;
        const float* hrow = nullptr;
        if (gn < NN)
            hrow = layer0 ? (node_emb + (size_t)x[gn] * HH)
                          : (d_h + (size_t)gn * HH);
#pragma unroll
        for (int i = 0; i < 8; i++) {
            int c4 = hoff + i;
            float4 hv = make_float4(0.f, 0.f, 0.f, 0.f);
            if (hrow) hv = *(const float4*)(hrow + c4 * 4);
            int c = c4 * 4;
            hs_t[(c + 0) * 128 + n] = hv.x;
            hs_t[(c + 1) * 128 + n] = hv.y;
            hs_t[(c + 2) * 128 + n] = hv.z;
            hs_t[(c + 3) * 128 + n] = hv.w;
        }
    }
#pragma unroll
    for (int i = 0; i < 4; i++) {
        int fidx = t * 4 + i;
        *(float4*)(ws + fidx * 4) = *(const float4*)(W + fidx * 4);
    }
    __syncthreads();

    int tx = t >> 4;
    int ty = t & 15;
    float acc[8][4];
#pragma unroll
    for (int u = 0; u < 8; u++)
#pragma unroll
        for (int w = 0; w < 4; w++) acc[u][w] = 0.f;

#pragma unroll 4
    for (int c = 0; c < 64; c++) {
        float4 a0 = *(const float4*)(hs_t + c * 128 + tx * 8);
        float4 a1 = *(const float4*)(hs_t + c * 128 + tx * 8 + 4);
        float4 b  = *(const float4*)(ws + c * 64 + ty * 4);
        float a[8] = {a0.x, a0.y, a0.z, a0.w, a1.x, a1.y, a1.z, a1.w};
        float bv4[4] = {b.x, b.y, b.z, b.w};
#pragma unroll
        for (int u = 0; u < 8; u++)
#pragma unroll
            for (int w = 0; w < 4; w++)
                acc[u][w] += a[u] * bv4[w];
    }

    float4 bb = *(const float4*)(bias + ty * 4);
#pragma unroll
    for (int u = 0; u < 8; u++) {
        int n = nodeBase + tx * 8 + u;
        if (n >= NN) continue;
        float c0 = acc[u][0] + bb.x;
        float c1 = acc[u][1] + bb.y;
        float c2 = acc[u][2] + bb.z;
        float c3 = acc[u][3] + bb.w;
        if (outF) {
            float4 o = make_float4(c0, c1, c2, c3);
            *(float4*)(outF + (size_t)n * HH + ty * 4) = o;
        } else {
            __half2 lo = __floats2half2_rn(c0, c1);
            __half2 hi = __floats2half2_rn(c2, c3);
            uint2 st;
            st.x = *(unsigned*)&lo;
            st.y = *(unsigned*)&hi;
            *(uint2*)(outH + (size_t)n * 32 + ty * 2) = st;
        }
    }
}

// ---------------- fused flash-style attention layer ---------------------------
// one warp per dst node; 4 edge-groups of 8 lanes; uniform trip counts;
// k/v gathered in fp16 (one LDG.128 per row per group).
__global__ void __launch_bounds__(256) attn_kernel(
        int layer, int do_gate,
        const float* __restrict__ gate_W, const float* __restrict__ gate_b,
        const int* __restrict__ batch) {
    __shared__ float ec_s[EDGE_CAT * HH];
    __shared__ float qe_s[8][16];
    const float* ec = d_ecat + layer * EDGE_CAT * HH;
    for (int i = threadIdx.x; i < EDGE_CAT * HH; i += 256)
        ec_s[i] = ec[i];
    __syncthreads();

    int wl = threadIdx.x >> 5;
    int n = blockIdx.x * 8 + wl;
    if (n >= NN) return;     // whole warp exits together
    int lane = threadIdx.x & 31;
    int g = lane >> 3;       // edge group 0..3
    int fl = lane & 7;       // feature slice (8 floats)

    const float* qr = d_q + (size_t)n * HH + fl * 8;
    float4 q0 = *(const float4*)qr;
    float4 q1 = *(const float4*)(qr + 4);

    // qe[cat] = q . ecat[cat]; 3 uniform iterations (cats g, g+4, g+8)
#pragma unroll
    for (int i = 0; i < 3; i++) {
        int cat = g + i * 4;
        bool valid = (cat < EDGE_CAT);
        int catc = valid ? cat : 0;
        const float* er = ec_s + catc * HH + fl * 8;
        float4 e0 = *(const float4*)er, e1 = *(const float4*)(er + 4);
        float p = q0.x * e0.x + q0.y * e0.y + q0.z * e0.z + q0.w * e0.w +
                  q1.x * e1.x + q1.y * e1.y + q1.z * e1.z + q1.w * e1.w;
        p += __shfl_xor_sync(0xffffffffu, p, 1);
        p += __shfl_xor_sync(0xffffffffu, p, 2);
        p += __shfl_xor_sync(0xffffffffu, p, 4);
        if (valid && fl == 0) qe_s[wl][cat] = p;
    }
    __syncwarp();

    int beg = d_rowptr[n], end = d_rowptr[n + 1];
    int nIter = (end - beg + 3) >> 2;
    float m = -1e30f, ssum = 0.f;
    float4 acc0 = make_float4(0.f, 0.f, 0.f, 0.f);
    float4 acc1 = make_float4(0.f, 0.f, 0.f, 0.f);

    for (int it = 0; it < nIter; it++) {
        int p = beg + it * 4 + g;
        bool valid = (p < end);
        int pc = valid ? p : beg;          // nIter>0 implies beg<end
        int packed = d_csr[pc];
        int s = packed & 0xffff;
        int cat = packed >> 16;
        uint4 kk = *(const uint4*)(d_k16 + (size_t)s * 32 + fl * 4);
        uint4 vv = *(const uint4*)(d_v16 + (size_t)s * 32 + fl * 4);
        float2 kf0 = __half22float2(*(__half2*)&kk.x);
        float2 kf1 = __half22float2(*(__half2*)&kk.y);
        float2 kf2 = __half22float2(*(__half2*)&kk.z);
        float2 kf3 = __half22float2(*(__half2*)&kk.w);
        float dp = q0.x * kf0.x + q0.y * kf0.y + q0.z * kf1.x + q0.w * kf1.y +
                   q1.x * kf2.x + q1.y * kf2.y + q1.z * kf3.x + q1.w * kf3.y;
        dp += __shfl_xor_sync(0xffffffffu, dp, 1);
        dp += __shfl_xor_sync(0xffffffffu, dp, 2);
        dp += __shfl_xor_sync(0xffffffffu, dp, 4);
        float alpha = valid ? (dp + qe_s[wl][cat]) * SCALE : -1e30f;
        float w;
        if (alpha > m) {     // group-uniform branch
            float c = __expf(m - alpha);
            ssum *= c;
            acc0.x *= c; acc0.y *= c; acc0.z *= c; acc0.w *= c;
            acc1.x *= c; acc1.y *= c; acc1.z *= c; acc1.w *= c;
            m = alpha;
            w = 1.f;
        } else {
            w = __expf(alpha - m);
        }
        if (!valid) w = 0.f;
        ssum += w;
        float2 vf0 = __half22float2(*(__half2*)&vv.x);
        float2 vf1 = __half22float2(*(__half2*)&vv.y);
        float2 vf2 = __half22float2(*(__half2*)&vv.z);
        float2 vf3 = __half22float2(*(__half2*)&vv.w);
        const float* er = ec_s + cat * HH + fl * 8;
        float4 e0 = *(const float4*)er, e1 = *(const float4*)(er + 4);
        acc0.x += w * (vf0.x + e0.x);
        acc0.y += w * (vf0.y + e0.y);
        acc0.z += w * (vf1.x + e0.z);
        acc0.w += w * (vf1.y + e0.w);
        acc1.x += w * (vf2.x + e1.x);
        acc1.y += w * (vf2.y + e1.y);
        acc1.z += w * (vf3.x + e1.z);
        acc1.w += w * (vf3.y + e1.w);
    }

    // merge the 4 groups; afterwards every lane holds the merged state
#pragma unroll
    for (int o = 8; o <= 16; o <<= 1) {
        float mo = __shfl_xor_sync(0xffffffffu, m, o);
        float so = __shfl_xor_sync(0xffffffffu, ssum, o);
        float mn = fmaxf(m, mo);
        float cs = __expf(m - mn), co = __expf(mo - mn);
        ssum = ssum * cs + so * co;
        acc0.x = acc0.x * cs + __shfl_xor_sync(0xffffffffu, acc0.x, o) * co;
        acc0.y = acc0.y * cs + __shfl_xor_sync(0xffffffffu, acc0.y, o) * co;
        acc0.z = acc0.z * cs + __shfl_xor_sync(0xffffffffu, acc0.z, o) * co;
        acc0.w = acc0.w * cs + __shfl_xor_sync(0xffffffffu, acc0.w, o) * co;
        acc1.x = acc1.x * cs + __shfl_xor_sync(0xffffffffu, acc1.x, o) * co;
        acc1.y = acc1.y * cs + __shfl_xor_sync(0xffffffffu, acc1.y, o) * co;
        acc1.z = acc1.z * cs + __shfl_xor_sync(0xffffffffu, acc1.z, o) * co;
        acc1.w = acc1.w * cs + __shfl_xor_sync(0xffffffffu, acc1.w, o) * co;
        m = mn;
    }

    float inv = (ssum > 0.f) ? (1.f / ssum) : 0.f;
    const float* sr = d_s + (size_t)n * HH + fl * 8;
    float4 s0 = *(const float4*)sr, s1 = *(const float4*)(sr + 4);
    float4 h0, h1;
    h0.x = fmaxf(acc0.x * inv + s0.x, 0.f);
    h0.y = fmaxf(acc0.y * inv + s0.y, 0.f);
    h0.z = fmaxf(acc0.z * inv + s0.z, 0.f);
    h0.w = fmaxf(acc0.w * inv + s0.w, 0.f);
    h1.x = fmaxf(acc1.x * inv + s1.x, 0.f);
    h1.y = fmaxf(acc1.y * inv + s1.y, 0.f);
    h1.z = fmaxf(acc1.z * inv + s1.z, 0.f);
    h1.w = fmaxf(acc1.w * inv + s1.w, 0.f);
    if (g == 0) {
        *(float4*)(d_h + (size_t)n * HH + fl * 8) = h0;
        *(float4*)(d_h + (size_t)n * HH + fl * 8 + 4) = h1;
    }
    if (do_gate) {
        const float* gw = gate_W + fl * 8;
        float4 w0 = *(const float4*)gw, w1 = *(const float4*)(gw + 4);
        float gp = h0.x * w0.x + h0.y * w0.y + h0.z * w0.z + h0.w * w0.w +
                   h1.x * w1.x + h1.y * w1.y + h1.z * w1.z + h1.w * w1.w;
        gp += __shfl_xor_sync(0xffffffffu, gp, 1);
        gp += __shfl_xor_sync(0xffffffffu, gp, 2);
        gp += __shfl_xor_sync(0xffffffffu, gp, 4);
        if (lane == 0) {
            float gv = gp + gate_b[0];
            d_gate[n] = gv;
            atomicMax(&d_gmax[batch[n]], enc_f(gv));
        }
    }
}

// ---------------- readout -----------------------------------------------------

__global__ void readout_init_kernel(float* __restrict__ out) {
    int i = blockIdx.x * blockDim.x + threadIdx.x;
    if (i < GG * OUTD) out[i] = 0.f;
    if (i < GG) {
        d_gmax[i] = ENC_NEG_INF;
        d_gdenom[i] = 0.f;
    }
}

__global__ void gexp_kernel(const int* __restrict__ batch) {
    int n = blockIdx.x * blockDim.x + threadIdx.x;
    if (n >= NN) return;
    int b = batch[n];
    float g = __expf(d_gate[n] - dec_f(d_gmax[b]));
    d_gate[n] = g;
    atomicAdd(&d_gdenom[b], g);
}

__global__ void out_kernel(const int* __restrict__ batch,
                           const float* __restrict__ out_W,
                           const float* __restrict__ out_b,
                           float* __restrict__ out) {
    __shared__ float ow[HH * OUTD];   // 8KB
    __shared__ float hs[8][HH];
    int t = threadIdx.x;
    for (int i = t; i < HH * OUTD; i += 256) ow[i] = out_W[i];
    for (int i = t; i < 8 * HH; i += 256) {
        int r = i >> 6, c = i & 63;
        int n2 = blockIdx.x * 8 + r;
        hs[r][c] = (n2 < NN) ? d_h[n2 * HH + c] : 0.f;
    }
    __syncthreads();
    int j = t & 31, g = t >> 5;
    int n = blockIdx.x * 8 + g;
    if (n >= NN) return;
    float acc = out_b[j];
#pragma unroll
    for (int c = 0; c < HH; c++) acc += hs[g][c] * ow[c * OUTD + j];
    int b = batch[n];
    float w = d_gate[n] / d_gdenom[b];
    atomicAdd(&out[b * OUTD + j], w * acc);
}

// ---------------- launch -----------------------------------------------------

extern "C" void kernel_launch(void* const* d_in, const int* in_sizes, int n_in,
                              void* d_out, int out_size) {
    const int* x          = (const int*)d_in[0];
    const int* edge_index = (const int*)d_in[1];
    const int* src        = edge_index;
    const int* dst        = edge_index + EE;
    const int* ea         = (const int*)d_in[2];
    const int* batch      = (const int*)d_in[3];
    const float* node_emb = (const float*)d_in[4];
    const float* edge_emb = (const float*)d_in[5];
    const float* Wq       = (const float*)d_in[6];
    const float* Wk       = (const float*)d_in[7];
    const float* Wv       = (const float*)d_in[8];
    const float* We       = (const float*)d_in[9];
    const float* Wskip    = (const float*)d_in[10];
    const float* bq       = (const float*)d_in[11];
    const float* bk       = (const float*)d_in[12];
    const float* bv       = (const float*)d_in[13];
    const float* bskip    = (const float*)d_in[14];
    const float* gate_W   = (const float*)d_in[15];
    const float* gate_b   = (const float*)d_in[16];
    const float* out_W    = (const float*)d_in[17];
    const float* out_b    = (const float*)d_in[18];
    float* out            = (float*)d_out;

    const int E_BLOCKS  = (EE + 255) / 256;
    const int N_BLOCKS  = (NN + 255) / 256;
    const int SCAN_BLOCKS = (NN + 1023) / 1024;

    // CSR build (by dst)
    hist_init_kernel<<<N_BLOCKS, 256>>>();
    hist_kernel<<<E_BLOCKS, 256>>>(dst);
    scan_blocks_kernel<<<SCAN_BLOCKS, 1024>>>();
    scan_tops_kernel<<<1, 64>>>();
    scan_add_kernel<<<(NN + 1 + 1023) / 1024, 1024>>>();
    scatter_kernel<<<E_BLOCKS, 256>>>(src, dst, ea);

    ecat_kernel<<<LL * EDGE_CAT, HH>>>(edge_emb, We);

    dim3 gemm_grid((NN + 127) / 128, 4);
    const int ATTN_BLOCKS = (NN + 7) / 8;
    for (int l = 0; l < LL; l++) {
        if (l == LL - 1)
            readout_init_kernel<<<(GG * OUTD + 255) / 256, 256>>>(out);
        proj_gemm<<<gemm_grid, 256>>>(
            Wq + (size_t)l * HH * HH, Wk + (size_t)l * HH * HH,
            Wv + (size_t)l * HH * HH, Wskip + (size_t)l * HH * HH,
            bq + (size_t)l * HH, bk + (size_t)l * HH,
            bv + (size_t)l * HH, bskip + (size_t)l * HH,
            x, node_emb, (l == 0) ? 1 : 0);
        attn_kernel<<<ATTN_BLOCKS, 256>>>(l, (l == LL - 1) ? 1 : 0,
                                          gate_W, gate_b, batch);
    }

    gexp_kernel<<<N_BLOCKS, 256>>>(batch);
    out_kernel<<<(NN + 7) / 8, 256>>>(batch, out_W, out_b, out);
}

// round 11
// speedup vs baseline: 1.2521x; 1.1189x over previous
#include <cuda_runtime.h>
#include <cuda_bf16.h>
#include <cuda_fp16.h>

// Problem constants (fixed by the reference)
#define NN 50000
#define EE 800000
#define HH 64
#define EDD 32
#define LL 3
#define GG 256
#define OUTD 32
#define EDGE_CAT 10
#define SCALE 0.125f  // 1/sqrt(64)

// ---------------- scratch (device globals; no allocation allowed) -----------
__device__ float d_h[NN * HH];
__device__ float d_q[NN * HH];
__device__ float d_s[NN * HH];        // skip projection h@Wskip + bskip
__device__ __half2 d_k16[NN * 32];    // fp16 keys   (64 halves per node)
__device__ __half2 d_v16[NN * 32];    // fp16 values
__device__ float d_ecat[LL * EDGE_CAT * HH];
__device__ float d_gate[NN];
__device__ unsigned d_gmax[GG];
__device__ float d_gdenom[GG];
// CSR scratch
__device__ int d_deg[NN];
__device__ int d_rowptr[NN + 1];
__device__ int d_wp[NN];
__device__ int d_csr[EE];             // packed: src | (cat<<16)
__device__ int d_bsum[64];
__device__ int d_bpre[65];

// order-preserving float<->uint encoding for atomicMax on floats
#define ENC_NEG_INF 0x007fffffu
__device__ __forceinline__ unsigned enc_f(float f) {
    unsigned b = __float_as_uint(f);
    return (b & 0x80000000u) ? ~b : (b | 0x80000000u);
}
__device__ __forceinline__ float dec_f(unsigned u) {
    unsigned b = (u & 0x80000000u) ? (u & 0x7fffffffu) : ~u;
    return __uint_as_float(b);
}

__device__ __forceinline__ float tf32r(float x) {
    float r;
    asm("cvt.rna.tf32.f32 %0, %1;" : "=f"(r) : "f"(x));
    return r;
}

// ---------------- CSR build --------------------------------------------------

__global__ void hist_init_kernel() {
    int i = blockIdx.x * blockDim.x + threadIdx.x;
    if (i < NN) d_deg[i] = 0;
}

__global__ void hist_kernel(const int* __restrict__ dst) {
    int e = blockIdx.x * blockDim.x + threadIdx.x;
    if (e < EE) atomicAdd(&d_deg[dst[e]], 1);
}

// block-local exclusive scan; block totals to d_bsum
__global__ void scan_blocks_kernel() {
    __shared__ int wsum[32];
    int t = threadIdx.x, lane = t & 31, w = t >> 5;
    int i = blockIdx.x * 1024 + t;
    int v = (i < NN) ? d_deg[i] : 0;
    int x = v;
#pragma unroll
    for (int o = 1; o < 32; o <<= 1) {
        int y = __shfl_up_sync(0xffffffffu, x, o);
        if (lane >= o) x += y;
    }
    if (lane == 31) wsum[w] = x;
    __syncthreads();
    if (w == 0) {
        int ws = wsum[lane];
#pragma unroll
        for (int o = 1; o < 32; o <<= 1) {
            int y = __shfl_up_sync(0xffffffffu, ws, o);
            if (lane >= o) ws += y;
        }
        wsum[lane] = ws;
    }
    __syncthreads();
    int incl = x + (w > 0 ? wsum[w - 1] : 0);
    if (i < NN) d_rowptr[i] = incl - v;
    if (t == 1023) d_bsum[blockIdx.x] = incl;
}

// combined setup kernel (256 threads, 64 blocks):
//   block 0        : scan of block totals (needs scan_blocks done)
//   blocks 1..30   : ecat for (layer, cat) = blockIdx.x-1
//   blocks 31..63  : zero output + init graph softmax state
__global__ void setup_kernel(float* __restrict__ out,
                             const float* __restrict__ edge_emb,
                             const float* __restrict__ We) {
    int t = threadIdx.x;
    if (blockIdx.x == 0) {
        __shared__ int tmp[64];
        int nb = (NN + 1023) / 1024;
        if (t < 64) tmp[t] = (t < nb) ? d_bsum[t] : 0;
        __syncthreads();
        for (int o = 1; o < 64; o <<= 1) {
            int a = (t < 64 && t >= o) ? tmp[t - o] : 0;
            __syncthreads();
            if (t < 64) tmp[t] += a;
            __syncthreads();
        }
        if (t < 64) d_bpre[t + 1] = tmp[t];
        if (t == 0) d_bpre[0] = 0;
    } else if (blockIdx.x <= LL * EDGE_CAT) {
        int id = blockIdx.x - 1;
        int l = id / EDGE_CAT;
        int cat = id % EDGE_CAT;
        if (t < HH) {
            const float* W = We + (size_t)l * EDD * HH;
            float acc = 0.f;
#pragma unroll
            for (int c = 0; c < EDD; c++)
                acc += edge_emb[cat * EDD + c] * W[c * HH + t];
            d_ecat[(l * EDGE_CAT + cat) * HH + t] = acc;
        }
    } else {
        int i = (blockIdx.x - 31) * 256 + t;
        if (i < GG * OUTD) out[i] = 0.f;
        if (i < GG) {
            d_gmax[i] = ENC_NEG_INF;
            d_gdenom[i] = 0.f;
        }
    }
}

__global__ void scan_add_kernel() {
    int i = blockIdx.x * blockDim.x + threadIdx.x;
    if (i < NN) {
        int r = d_rowptr[i] + d_bpre[i >> 10];
        d_rowptr[i] = r;
        d_wp[i] = r;
    } else if (i == NN) {
        d_rowptr[NN] = d_bpre[(NN + 1023) >> 10];
    }
}

__global__ void scatter_kernel(const int* __restrict__ src,
                               const int* __restrict__ dst,
                               const int* __restrict__ ea) {
    int e = blockIdx.x * blockDim.x + threadIdx.x;
    if (e >= EE) return;
    int d = dst[e];
    int pos = atomicAdd(&d_wp[d], 1);
    d_csr[pos] = src[e] | (ea[e] << 16);
}

// ---------------- tensor-core projection GEMM (tf32 mma) ----------------------
// blockIdx.y: 0=q(fp32) 1=skip(fp32) 2=k(fp16) 3=v(fp16)
// BM=64 nodes per block, full K=64, N=64 cols. 256 threads = 8 warps.
// warp -> (m-tile = warp&3 : 16 nodes, n-half = warp>>2 : 32 cols).
// smem rows padded to 72 floats -> fragment loads are bank-conflict-free.
__global__ void __launch_bounds__(256, 2)
proj_tc(const float* __restrict__ Wq, const float* __restrict__ Wk,
        const float* __restrict__ Wv, const float* __restrict__ Ws,
        const float* __restrict__ bq, const float* __restrict__ bk,
        const float* __restrict__ bv, const float* __restrict__ bs,
        const int* __restrict__ x, const float* __restrict__ node_emb,
        int layer0) {
    __shared__ float hsT[64][72];   // [k][node], tf32-rounded
    __shared__ float ws[64][72];    // [k][col],  tf32-rounded

    const float* W;
    const float* bias;
    float* outF = nullptr;
    __half2* outH = nullptr;
    switch (blockIdx.y) {
        case 0:  W = Wq; bias = bq; outF = d_q;   break;
        case 1:  W = Ws; bias = bs; outF = d_s;   break;
        case 2:  W = Wk; bias = bk; outH = d_k16; break;
        default: W = Wv; bias = bv; outH = d_v16; break;
    }

    int t = threadIdx.x;
    int nodeBase = blockIdx.x * 64;

    // fill hsT (transposed h tile): thread t -> node t>>2, k-quarter (t&3)*16
    {
        int node = t >> 2;
        int k0 = (t & 3) * 16;
        int gn = nodeBase + node;
        const float* hrow = nullptr;
        if (gn < NN)
            hrow = layer0 ? (node_emb + (size_t)x[gn] * HH)
                          : (d_h + (size_t)gn * HH);
#pragma unroll
        for (int i = 0; i < 4; i++) {
            float4 hv = make_float4(0.f, 0.f, 0.f, 0.f);
            if (hrow) hv = *(const float4*)(hrow + k0 + i * 4);
            int k = k0 + i * 4;
            hsT[k + 0][node] = tf32r(hv.x);
            hsT[k + 1][node] = tf32r(hv.y);
            hsT[k + 2][node] = tf32r(hv.z);
            hsT[k + 3][node] = tf32r(hv.w);
        }
    }
    // fill ws: thread t -> k-row t>>2, col-quarter (t&3)*16
    {
        int r = t >> 2;
        int c0 = (t & 3) * 16;
#pragma unroll
        for (int i = 0; i < 4; i++) {
            float4 wv = *(const float4*)(W + r * 64 + c0 + i * 4);
            int c = c0 + i * 4;
            ws[r][c + 0] = tf32r(wv.x);
            ws[r][c + 1] = tf32r(wv.y);
            ws[r][c + 2] = tf32r(wv.z);
            ws[r][c + 3] = tf32r(wv.w);
        }
    }
    __syncthreads();

    int warp = t >> 5, lane = t & 31;
    int mb = (warp & 3) * 16;       // node tile base within block
    int nh = warp >> 2;             // col half (0/1)
    int gid = lane >> 2, tig = lane & 3;

    float d[4][4];
#pragma unroll
    for (int nt = 0; nt < 4; nt++)
#pragma unroll
        for (int i = 0; i < 4; i++) d[nt][i] = 0.f;

#pragma unroll
    for (int kc = 0; kc < 8; kc++) {
        int kr = kc * 8;
        unsigned a0 = __float_as_uint(hsT[kr + tig][mb + gid]);
        unsigned a1 = __float_as_uint(hsT[kr + tig][mb + gid + 8]);
        unsigned a2 = __float_as_uint(hsT[kr + tig + 4][mb + gid]);
        unsigned a3 = __float_as_uint(hsT[kr + tig + 4][mb + gid + 8]);
#pragma unroll
        for (int nt = 0; nt < 4; nt++) {
            int nb = nh * 32 + nt * 8;
            unsigned b0 = __float_as_uint(ws[kr + tig][nb + gid]);
            unsigned b1 = __float_as_uint(ws[kr + tig + 4][nb + gid]);
            asm("mma.sync.aligned.m16n8k8.row.col.f32.tf32.tf32.f32 "
                "{%0,%1,%2,%3},{%4,%5,%6,%7},{%8,%9},{%0,%1,%2,%3};"
                : "+f"(d[nt][0]), "+f"(d[nt][1]), "+f"(d[nt][2]), "+f"(d[nt][3])
                : "r"(a0), "r"(a1), "r"(a2), "r"(a3), "r"(b0), "r"(b1));
        }
    }

    int n0 = nodeBase + mb + gid;
    int n1 = n0 + 8;
#pragma unroll
    for (int nt = 0; nt < 4; nt++) {
        int col = nh * 32 + nt * 8 + 2 * tig;
        float b0f = bias[col], b1f = bias[col + 1];
        float c0 = d[nt][0] + b0f, c1 = d[nt][1] + b1f;
        float c2 = d[nt][2] + b0f, c3 = d[nt][3] + b1f;
        if (outF) {
            if (n0 < NN) *(float2*)(outF + (size_t)n0 * HH + col) = make_float2(c0, c1);
            if (n1 < NN) *(float2*)(outF + (size_t)n1 * HH + col) = make_float2(c2, c3);
        } else {
            if (n0 < NN) outH[(size_t)n0 * 32 + (col >> 1)] = __floats2half2_rn(c0, c1);
            if (n1 < NN) outH[(size_t)n1 * 32 + (col >> 1)] = __floats2half2_rn(c2, c3);
        }
    }
}

// ---------------- fused flash-style attention layer ---------------------------
// one warp per dst node; 4 edge-groups of 8 lanes; uniform trip counts;
// k/v gathered in fp16 (one LDG.128 per row per group).
__global__ void __launch_bounds__(256) attn_kernel(
        int layer, int do_gate,
        const float* __restrict__ gate_W, const float* __restrict__ gate_b,
        const int* __restrict__ batch) {
    __shared__ float ec_s[EDGE_CAT * HH];
    __shared__ float qe_s[8][16];
    const float* ec = d_ecat + layer * EDGE_CAT * HH;
    for (int i = threadIdx.x; i < EDGE_CAT * HH; i += 256)
        ec_s[i] = ec[i];
    __syncthreads();

    int wl = threadIdx.x >> 5;
    int n = blockIdx.x * 8 + wl;
    if (n >= NN) return;     // whole warp exits together
    int lane = threadIdx.x & 31;
    int g = lane >> 3;       // edge group 0..3
    int fl = lane & 7;       // feature slice (8 floats)

    const float* qr = d_q + (size_t)n * HH + fl * 8;
    float4 q0 = *(const float4*)qr;
    float4 q1 = *(const float4*)(qr + 4);

    // qe[cat] = q . ecat[cat]; 3 uniform iterations (cats g, g+4, g+8)
#pragma unroll
    for (int i = 0; i < 3; i++) {
        int cat = g + i * 4;
        bool valid = (cat < EDGE_CAT);
        int catc = valid ? cat : 0;
        const float* er = ec_s + catc * HH + fl * 8;
        float4 e0 = *(const float4*)er, e1 = *(const float4*)(er + 4);
        float p = q0.x * e0.x + q0.y * e0.y + q0.z * e0.z + q0.w * e0.w +
                  q1.x * e1.x + q1.y * e1.y + q1.z * e1.z + q1.w * e1.w;
        p += __shfl_xor_sync(0xffffffffu, p, 1);
        p += __shfl_xor_sync(0xffffffffu, p, 2);
        p += __shfl_xor_sync(0xffffffffu, p, 4);
        if (valid && fl == 0) qe_s[wl][cat] = p;
    }
    __syncwarp();

    int beg = d_rowptr[n], end = d_rowptr[n + 1];
    int nIter = (end - beg + 3) >> 2;
    float m = -1e30f, ssum = 0.f;
    float4 acc0 = make_float4(0.f, 0.f, 0.f, 0.f);
    float4 acc1 = make_float4(0.f, 0.f, 0.f, 0.f);

    for (int it = 0; it < nIter; it++) {
        int p = beg + it * 4 + g;
        bool valid = (p < end);
        int pc = valid ? p : beg;          // nIter>0 implies beg<end
        int packed = d_csr[pc];
        int s = packed & 0xffff;
        int cat = packed >> 16;
        uint4 kk = *(const uint4*)(d_k16 + (size_t)s * 32 + fl * 4);
        uint4 vv = *(const uint4*)(d_v16 + (size_t)s * 32 + fl * 4);
        float2 kf0 = __half22float2(*(__half2*)&kk.x);
        float2 kf1 = __half22float2(*(__half2*)&kk.y);
        float2 kf2 = __half22float2(*(__half2*)&kk.z);
        float2 kf3 = __half22float2(*(__half2*)&kk.w);
        float dp = q0.x * kf0.x + q0.y * kf0.y + q0.z * kf1.x + q0.w * kf1.y +
                   q1.x * kf2.x + q1.y * kf2.y + q1.z * kf3.x + q1.w * kf3.y;
        dp += __shfl_xor_sync(0xffffffffu, dp, 1);
        dp += __shfl_xor_sync(0xffffffffu, dp, 2);
        dp += __shfl_xor_sync(0xffffffffu, dp, 4);
        float alpha = valid ? (dp + qe_s[wl][cat]) * SCALE : -1e30f;
        float w;
        if (alpha > m) {     // group-uniform branch
            float c = __expf(m - alpha);
            ssum *= c;
            acc0.x *= c; acc0.y *= c; acc0.z *= c; acc0.w *= c;
            acc1.x *= c; acc1.y *= c; acc1.z *= c; acc1.w *= c;
            m = alpha;
            w = 1.f;
        } else {
            w = __expf(alpha - m);
        }
        if (!valid) w = 0.f;
        ssum += w;
        float2 vf0 = __half22float2(*(__half2*)&vv.x);
        float2 vf1 = __half22float2(*(__half2*)&vv.y);
        float2 vf2 = __half22float2(*(__half2*)&vv.z);
        float2 vf3 = __half22float2(*(__half2*)&vv.w);
        const float* er = ec_s + cat * HH + fl * 8;
        float4 e0 = *(const float4*)er, e1 = *(const float4*)(er + 4);
        acc0.x += w * (vf0.x + e0.x);
        acc0.y += w * (vf0.y + e0.y);
        acc0.z += w * (vf1.x + e0.z);
        acc0.w += w * (vf1.y + e0.w);
        acc1.x += w * (vf2.x + e1.x);
        acc1.y += w * (vf2.y + e1.y);
        acc1.z += w * (vf3.x + e1.z);
        acc1.w += w * (vf3.y + e1.w);
    }

    // merge the 4 groups; afterwards every lane holds the merged state
#pragma unroll
    for (int o = 8; o <= 16; o <<= 1) {
        float mo = __shfl_xor_sync(0xffffffffu, m, o);
        float so = __shfl_xor_sync(0xffffffffu, ssum, o);
        float mn = fmaxf(m, mo);
        float cs = __expf(m - mn), co = __expf(mo - mn);
        ssum = ssum * cs + so * co;
        acc0.x = acc0.x * cs + __shfl_xor_sync(0xffffffffu, acc0.x, o) * co;
        acc0.y = acc0.y * cs + __shfl_xor_sync(0xffffffffu, acc0.y, o) * co;
        acc0.z = acc0.z * cs + __shfl_xor_sync(0xffffffffu, acc0.z, o) * co;
        acc0.w = acc0.w * cs + __shfl_xor_sync(0xffffffffu, acc0.w, o) * co;
        acc1.x = acc1.x * cs + __shfl_xor_sync(0xffffffffu, acc1.x, o) * co;
        acc1.y = acc1.y * cs + __shfl_xor_sync(0xffffffffu, acc1.y, o) * co;
        acc1.z = acc1.z * cs + __shfl_xor_sync(0xffffffffu, acc1.z, o) * co;
        acc1.w = acc1.w * cs + __shfl_xor_sync(0xffffffffu, acc1.w, o) * co;
        m = mn;
    }

    float inv = (ssum > 0.f) ? (1.f / ssum) : 0.f;
    const float* sr = d_s + (size_t)n * HH + fl * 8;
    float4 s0 = *(const float4*)sr, s1 = *(const float4*)(sr + 4);
    float4 h0, h1;
    h0.x = fmaxf(acc0.x * inv + s0.x, 0.f);
    h0.y = fmaxf(acc0.y * inv + s0.y, 0.f);
    h0.z = fmaxf(acc0.z * inv + s0.z, 0.f);
    h0.w = fmaxf(acc0.w * inv + s0.w, 0.f);
    h1.x = fmaxf(acc1.x * inv + s1.x, 0.f);
    h1.y = fmaxf(acc1.y * inv + s1.y, 0.f);
    h1.z = fmaxf(acc1.z * inv + s1.z, 0.f);
    h1.w = fmaxf(acc1.w * inv + s1.w, 0.f);
    if (g == 0) {
        *(float4*)(d_h + (size_t)n * HH + fl * 8) = h0;
        *(float4*)(d_h + (size_t)n * HH + fl * 8 + 4) = h1;
    }
    if (do_gate) {
        const float* gw = gate_W + fl * 8;
        float4 w0 = *(const float4*)gw, w1 = *(const float4*)(gw + 4);
        float gp = h0.x * w0.x + h0.y * w0.y + h0.z * w0.z + h0.w * w0.w +
                   h1.x * w1.x + h1.y * w1.y + h1.z * w1.z + h1.w * w1.w;
        gp += __shfl_xor_sync(0xffffffffu, gp, 1);
        gp += __shfl_xor_sync(0xffffffffu, gp, 2);
        gp += __shfl_xor_sync(0xffffffffu, gp, 4);
        if (lane == 0) {
            float gv = gp + gate_b[0];
            d_gate[n] = gv;
            atomicMax(&d_gmax[batch[n]], enc_f(gv));
        }
    }
}

// ---------------- readout -----------------------------------------------------

__global__ void gexp_kernel(const int* __restrict__ batch) {
    int n = blockIdx.x * blockDim.x + threadIdx.x;
    if (n >= NN) return;
    int b = batch[n];
    float g = __expf(d_gate[n] - dec_f(d_gmax[b]));
    d_gate[n] = g;
    atomicAdd(&d_gdenom[b], g);
}

__global__ void out_kernel(const int* __restrict__ batch,
                           const float* __restrict__ out_W,
                           const float* __restrict__ out_b,
                           float* __restrict__ out) {
    __shared__ float ow[HH * OUTD];   // 8KB
    __shared__ float hs[8][HH];
    int t = threadIdx.x;
    for (int i = t; i < HH * OUTD; i += 256) ow[i] = out_W[i];
    for (int i = t; i < 8 * HH; i += 256) {
        int r = i >> 6, c = i & 63;
        int n2 = blockIdx.x * 8 + r;
        hs[r][c] = (n2 < NN) ? d_h[n2 * HH + c] : 0.f;
    }
    __syncthreads();
    int j = t & 31, g = t >> 5;
    int n = blockIdx.x * 8 + g;
    if (n >= NN) return;
    float acc = out_b[j];
#pragma unroll
    for (int c = 0; c < HH; c++) acc += hs[g][c] * ow[c * OUTD + j];
    int b = batch[n];
    float w = d_gate[n] / d_gdenom[b];
    atomicAdd(&out[b * OUTD + j], w * acc);
}

// ---------------- launch -----------------------------------------------------

extern "C" void kernel_launch(void* const* d_in, const int* in_sizes, int n_in,
                              void* d_out, int out_size) {
    const int* x          = (const int*)d_in[0];
    const int* edge_index = (const int*)d_in[1];
    const int* src        = edge_index;
    const int* dst        = edge_index + EE;
    const int* ea         = (const int*)d_in[2];
    const int* batch      = (const int*)d_in[3];
    const float* node_emb = (const float*)d_in[4];
    const float* edge_emb = (const float*)d_in[5];
    const float* Wq       = (const float*)d_in[6];
    const float* Wk       = (const float*)d_in[7];
    const float* Wv       = (const float*)d_in[8];
    const float* We       = (const float*)d_in[9];
    const float* Wskip    = (const float*)d_in[10];
    const float* bq       = (const float*)d_in[11];
    const float* bk       = (const float*)d_in[12];
    const float* bv       = (const float*)d_in[13];
    const float* bskip    = (const float*)d_in[14];
    const float* gate_W   = (const float*)d_in[15];
    const float* gate_b   = (const float*)d_in[16];
    const float* out_W    = (const float*)d_in[17];
    const float* out_b    = (const float*)d_in[18];
    float* out            = (float*)d_out;

    const int E_BLOCKS  = (EE + 255) / 256;
    const int N_BLOCKS  = (NN + 255) / 256;
    const int SCAN_BLOCKS = (NN + 1023) / 1024;

    // CSR build (by dst)
    hist_init_kernel<<<N_BLOCKS, 256>>>();
    hist_kernel<<<E_BLOCKS, 256>>>(dst);
    scan_blocks_kernel<<<SCAN_BLOCKS, 1024>>>();
    setup_kernel<<<64, 256>>>(out, edge_emb, We);   // scan_tops + ecat + readout init
    scan_add_kernel<<<(NN + 1 + 1023) / 1024, 1024>>>();
    scatter_kernel<<<E_BLOCKS, 256>>>(src, dst, ea);

    dim3 gemm_grid((NN + 63) / 64, 4);
    const int ATTN_BLOCKS = (NN + 7) / 8;
    for (int l = 0; l < LL; l++) {
        proj_tc<<<gemm_grid, 256>>>(
            Wq + (size_t)l * HH * HH, Wk + (size_t)l * HH * HH,
            Wv + (size_t)l * HH * HH, Wskip + (size_t)l * HH * HH,
            bq + (size_t)l * HH, bk + (size_t)l * HH,
            bv + (size_t)l * HH, bskip + (size_t)l * HH,
            x, node_emb, (l == 0) ? 1 : 0);
        attn_kernel<<<ATTN_BLOCKS, 256>>>(l, (l == LL - 1) ? 1 : 0,
                                          gate_W, gate_b, batch);
    }

    gexp_kernel<<<N_BLOCKS, 256>>>(batch);
    out_kernel<<<(NN + 7) / 8, 256>>>(batch, out_W, out_b, out);
}

// round 13
// speedup vs baseline: 1.2592x; 1.0056x over previous
#include <cuda_runtime.h>
#include <cuda_bf16.h>
#include <cuda_fp16.h>

// Problem constants (fixed by the reference)
#define NN 50000
#define EE 800000
#define HH 64
#define EDD 32
#define LL 3
#define GG 256
#define OUTD 32
#define EDGE_CAT 10
#define SCALE 0.125f  // 1/sqrt(64)

#define PROJ_BX ((NN + 63) / 64)     // 782 proj blocks per matrix
#define PROJ_BLOCKS (PROJ_BX * 4)    // 3128
#define E_BLOCKS ((EE + 255) / 256)  // 3125

// ---------------- scratch (device globals; no allocation allowed) -----------
__device__ float d_h[NN * HH];
__device__ float d_q[NN * HH];
__device__ float d_s[NN * HH];        // skip projection h@Wskip + bskip
__device__ __half2 d_k16[NN * 32];    // fp16 keys   (64 halves per node)
__device__ __half2 d_v16[NN * 32];    // fp16 values
__device__ float d_ecat[LL * EDGE_CAT * HH];
__device__ float d_gate[NN];
__device__ unsigned d_gmax[GG];
__device__ float d_gdenom[GG];
// CSR scratch (d_deg zero at module load; scan_blocks restores the invariant)
__device__ int d_deg[NN];
__device__ int d_rowptr[NN + 1];      // block-LOCAL exclusive prefixes
__device__ int d_wp[NN];              // working copy of local prefixes
__device__ int d_csr[EE];             // packed: src | (cat<<16)
__device__ int d_bsum[64];
__device__ int d_bpre[65];            // global prefix of 1024-node blocks

// order-preserving float<->uint encoding for atomicMax on floats
#define ENC_NEG_INF 0x007fffffu
__device__ __forceinline__ unsigned enc_f(float f) {
    unsigned b = __float_as_uint(f);
    return (b & 0x80000000u) ? ~b : (b | 0x80000000u);
}
__device__ __forceinline__ float dec_f(unsigned u) {
    unsigned b = (u & 0x80000000u) ? (u & 0x7fffffffu) : ~u;
    return __uint_as_float(b);
}

__device__ __forceinline__ float tf32r(float x) {
    float r;
    asm("cvt.rna.tf32.f32 %0, %1;" : "=f"(r) : "f"(x));
    return r;
}

// ---------------- CSR build --------------------------------------------------

__global__ void hist_kernel(const int* __restrict__ dst) {
    int e = blockIdx.x * blockDim.x + threadIdx.x;
    if (e < EE) atomicAdd(&d_deg[dst[e]], 1);
}

// block-local exclusive scan; block totals to d_bsum; restores d_deg zeros
__global__ void scan_blocks_kernel() {
    __shared__ int wsum[32];
    int t = threadIdx.x, lane = t & 31, w = t >> 5;
    int i = blockIdx.x * 1024 + t;
    int v = (i < NN) ? d_deg[i] : 0;
    if (i < NN) d_deg[i] = 0;          // restore zero invariant
    int x = v;
#pragma unroll
    for (int o = 1; o < 32; o <<= 1) {
        int y = __shfl_up_sync(0xffffffffu, x, o);
        if (lane >= o) x += y;
    }
    if (lane == 31) wsum[w] = x;
    __syncthreads();
    if (w == 0) {
        int ws = wsum[lane];
#pragma unroll
        for (int o = 1; o < 32; o <<= 1) {
            int y = __shfl_up_sync(0xffffffffu, ws, o);
            if (lane >= o) ws += y;
        }
        wsum[lane] = ws;
    }
    __syncthreads();
    int incl = x + (w > 0 ? wsum[w - 1] : 0);
    if (i <= NN) d_rowptr[i] = incl - v;   // includes partial[NN]
    if (i < NN) d_wp[i] = incl - v;
    if (t == 1023) d_bsum[blockIdx.x] = incl;
}

// combined setup kernel (256 threads, 64 blocks):
//   block 0        : scan of block totals -> d_bpre
//   blocks 1..30   : ecat for (layer, cat) = blockIdx.x-1
//   blocks 31..63  : zero output + init graph softmax state
__global__ void setup_kernel(float* __restrict__ out,
                             const float* __restrict__ edge_emb,
                             const float* __restrict__ We) {
    int t = threadIdx.x;
    if (blockIdx.x == 0) {
        __shared__ int tmp[64];
        int nb = (NN + 1023) / 1024;
        if (t < 64) tmp[t] = (t < nb) ? d_bsum[t] : 0;
        __syncthreads();
        for (int o = 1; o < 64; o <<= 1) {
            int a = (t < 64 && t >= o) ? tmp[t - o] : 0;
            __syncthreads();
            if (t < 64) tmp[t] += a;
            __syncthreads();
        }
        if (t < 64) d_bpre[t + 1] = tmp[t];
        if (t == 0) d_bpre[0] = 0;
    } else if (blockIdx.x <= LL * EDGE_CAT) {
        int id = blockIdx.x - 1;
        int l = id / EDGE_CAT;
        int cat = id % EDGE_CAT;
        if (t < HH) {
            const float* W = We + (size_t)l * EDD * HH;
            float acc = 0.f;
#pragma unroll
            for (int c = 0; c < EDD; c++)
                acc += edge_emb[cat * EDD + c] * W[c * HH + t];
            d_ecat[(l * EDGE_CAT + cat) * HH + t] = acc;
        }
    } else {
        int i = (blockIdx.x - 31) * 256 + t;
        if (i < GG * OUTD) out[i] = 0.f;
        if (i < GG) {
            d_gmax[i] = ENC_NEG_INF;
            d_gdenom[i] = 0.f;
        }
    }
}

// ---------------- tensor-core projection body (tf32 mma) ----------------------
// by: 0=q(fp32) 1=skip(fp32) 2=k(fp16) 3=v(fp16)
// BM=64 nodes, full K=64, N=64. 256 threads = 8 warps.
__device__ __forceinline__ void proj_body(
        int bx, int by,
        const float* __restrict__ Wq, const float* __restrict__ Wk,
        const float* __restrict__ Wv, const float* __restrict__ Ws,
        const float* __restrict__ bq, const float* __restrict__ bk,
        const float* __restrict__ bv, const float* __restrict__ bs,
        const int* __restrict__ x, const float* __restrict__ node_emb,
        int layer0) {
    __shared__ float hsT[64][72];   // [k][node], tf32-rounded
    __shared__ float ws[64][72];    // [k][col],  tf32-rounded

    const float* W;
    const float* bias;
    float* outF = nullptr;
    __half2* outH = nullptr;
    switch (by) {
        case 0:  W = Wq; bias = bq; outF = d_q;   break;
        case 1:  W = Ws; bias = bs; outF = d_s;   break;
        case 2:  W = Wk; bias = bk; outH = d_k16; break;
        default: W = Wv; bias = bv; outH = d_v16; break;
    }

    int t = threadIdx.x;
    int nodeBase = bx * 64;

    // fill hsT (transposed h tile): thread t -> node t>>2, k-quarter (t&3)*16
    {
        int node = t >> 2;
        int k0 = (t & 3) * 16;
        int gn = nodeBase + node;
        const float* hrow = nullptr;
        if (gn < NN)
            hrow = layer0 ? (node_emb + (size_t)x[gn] * HH)
                          : (d_h + (size_t)gn * HH);
#pragma unroll
        for (int i = 0; i < 4; i++) {
            float4 hv = make_float4(0.f, 0.f, 0.f, 0.f);
            if (hrow) hv = *(const float4*)(hrow + k0 + i * 4);
            int k = k0 + i * 4;
            hsT[k + 0][node] = tf32r(hv.x);
            hsT[k + 1][node] = tf32r(hv.y);
            hsT[k + 2][node] = tf32r(hv.z);
            hsT[k + 3][node] = tf32r(hv.w);
        }
    }
    // fill ws: thread t -> k-row t>>2, col-quarter (t&3)*16
    {
        int r = t >> 2;
        int c0 = (t & 3) * 16;
#pragma unroll
        for (int i = 0; i < 4; i++) {
            float4 wv = *(const float4*)(W + r * 64 + c0 + i * 4);
            int c = c0 + i * 4;
            ws[r][c + 0] = tf32r(wv.x);
            ws[r][c + 1] = tf32r(wv.y);
            ws[r][c + 2] = tf32r(wv.z);
            ws[r][c + 3] = tf32r(wv.w);
        }
    }
    __syncthreads();

    int warp = t >> 5, lane = t & 31;
    int mb = (warp & 3) * 16;       // node tile base within block
    int nh = warp >> 2;             // col half (0/1)
    int gid = lane >> 2, tig = lane & 3;

    float d[4][4];
#pragma unroll
    for (int nt = 0; nt < 4; nt++)
#pragma unroll
        for (int i = 0; i < 4; i++) d[nt][i] = 0.f;

#pragma unroll
    for (int kc = 0; kc < 8; kc++) {
        int kr = kc * 8;
        unsigned a0 = __float_as_uint(hsT[kr + tig][mb + gid]);
        unsigned a1 = __float_as_uint(hsT[kr + tig][mb + gid + 8]);
        unsigned a2 = __float_as_uint(hsT[kr + tig + 4][mb + gid]);
        unsigned a3 = __float_as_uint(hsT[kr + tig + 4][mb + gid + 8]);
#pragma unroll
        for (int nt = 0; nt < 4; nt++) {
            int nb = nh * 32 + nt * 8;
            unsigned b0 = __float_as_uint(ws[kr + tig][nb + gid]);
            unsigned b1 = __float_as_uint(ws[kr + tig + 4][nb + gid]);
            asm("mma.sync.aligned.m16n8k8.row.col.f32.tf32.tf32.f32 "
                "{%0,%1,%2,%3},{%4,%5,%6,%7},{%8,%9},{%0,%1,%2,%3};"
                : "+f"(d[nt][0]), "+f"(d[nt][1]), "+f"(d[nt][2]), "+f"(d[nt][3])
                : "r"(a0), "r"(a1), "r"(a2), "r"(a3), "r"(b0), "r"(b1));
        }
    }

    int n0 = nodeBase + mb + gid;
    int n1 = n0 + 8;
#pragma unroll
    for (int nt = 0; nt < 4; nt++) {
        int col = nh * 32 + nt * 8 + 2 * tig;
        float b0f = bias[col], b1f = bias[col + 1];
        float c0 = d[nt][0] + b0f, c1 = d[nt][1] + b1f;
        float c2 = d[nt][2] + b0f, c3 = d[nt][3] + b1f;
        if (outF) {
            if (n0 < NN) *(float2*)(outF + (size_t)n0 * HH + col) = make_float2(c0, c1);
            if (n1 < NN) *(float2*)(outF + (size_t)n1 * HH + col) = make_float2(c2, c3);
        } else {
            if (n0 < NN) outH[(size_t)n0 * 32 + (col >> 1)] = __floats2half2_rn(c0, c1);
            if (n1 < NN) outH[(size_t)n1 * 32 + (col >> 1)] = __floats2half2_rn(c2, c3);
        }
    }
}

// proj-only kernel for layers >= 1
__global__ void __launch_bounds__(256, 2)
proj_tc(const float* __restrict__ Wq, const float* __restrict__ Wk,
        const float* __restrict__ Wv, const float* __restrict__ Ws,
        const float* __restrict__ bq, const float* __restrict__ bk,
        const float* __restrict__ bv, const float* __restrict__ bs,
        const int* __restrict__ x, const float* __restrict__ node_emb,
        int layer0) {
    proj_body(blockIdx.x, blockIdx.y, Wq, Wk, Wv, Ws, bq, bk, bv, bs,
              x, node_emb, layer0);
}

// merged: proj layer 0 (blocks 0..PROJ_BLOCKS-1) || scatter (remaining blocks)
__global__ void __launch_bounds__(256, 2)
scatter_proj0_kernel(const int* __restrict__ src, const int* __restrict__ dst,
                     const int* __restrict__ ea,
                     const float* __restrict__ Wq, const float* __restrict__ Wk,
                     const float* __restrict__ Wv, const float* __restrict__ Ws,
                     const float* __restrict__ bq, const float* __restrict__ bk,
                     const float* __restrict__ bv, const float* __restrict__ bs,
                     const int* __restrict__ x, const float* __restrict__ node_emb) {
    if (blockIdx.x < PROJ_BLOCKS) {
        int by = blockIdx.x / PROJ_BX;
        int bx = blockIdx.x % PROJ_BX;
        proj_body(bx, by, Wq, Wk, Wv, Ws, bq, bk, bv, bs, x, node_emb, 1);
    } else {
        int e = (blockIdx.x - PROJ_BLOCKS) * 256 + threadIdx.x;
        if (e < EE) {
            int d = dst[e];
            int pos = atomicAdd(&d_wp[d], 1) + d_bpre[d >> 10];
            if (pos >= 0 && pos < EE)      // safety clamp (never OOB)
                d_csr[pos] = src[e] | (ea[e] << 16);
        }
    }
}

// ---------------- fused flash-style attention layer ---------------------------
// one warp per dst node; 4 edge-groups of 8 lanes; uniform trip counts;
// k/v gathered in fp16 (one LDG.128 per row per group).
__global__ void __launch_bounds__(256) attn_kernel(
        int layer, int do_gate,
        const float* __restrict__ gate_W, const float* __restrict__ gate_b,
        const int* __restrict__ batch) {
    __shared__ float ec_s[EDGE_CAT * HH];
    __shared__ float qe_s[8][16];
    const float* ec = d_ecat + layer * EDGE_CAT * HH;
    for (int i = threadIdx.x; i < EDGE_CAT * HH; i += 256)
        ec_s[i] = ec[i];
    __syncthreads();

    int wl = threadIdx.x >> 5;
    int n = blockIdx.x * 8 + wl;
    if (n >= NN) return;     // whole warp exits together
    int lane = threadIdx.x & 31;
    int g = lane >> 3;       // edge group 0..3
    int fl = lane & 7;       // feature slice (8 floats)

    const float* qr = d_q + (size_t)n * HH + fl * 8;
    float4 q0 = *(const float4*)qr;
    float4 q1 = *(const float4*)(qr + 4);

    // qe[cat] = q . ecat[cat]; 3 uniform iterations (cats g, g+4, g+8)
#pragma unroll
    for (int i = 0; i < 3; i++) {
        int cat = g + i * 4;
        bool valid = (cat < EDGE_CAT);
        int catc = valid ? cat : 0;
        const float* er = ec_s + catc * HH + fl * 8;
        float4 e0 = *(const float4*)er, e1 = *(const float4*)(er + 4);
        float p = q0.x * e0.x + q0.y * e0.y + q0.z * e0.z + q0.w * e0.w +
                  q1.x * e1.x + q1.y * e1.y + q1.z * e1.z + q1.w * e1.w;
        p += __shfl_xor_sync(0xffffffffu, p, 1);
        p += __shfl_xor_sync(0xffffffffu, p, 2);
        p += __shfl_xor_sync(0xffffffffu, p, 4);
        if (valid && fl == 0) qe_s[wl][cat] = p;
    }
    __syncwarp();

    int beg = d_rowptr[n] + d_bpre[n >> 10];
    int end = d_rowptr[n + 1] + d_bpre[(n + 1) >> 10];
    int deg = end - beg;
    if (deg < 0 || deg > EE || beg < 0 || beg >= EE + 1) deg = 0;  // safety clamp
    int nIter = (deg + 3) >> 2;
    float m = -1e30f, ssum = 0.f;
    float4 acc0 = make_float4(0.f, 0.f, 0.f, 0.f);
    float4 acc1 = make_float4(0.f, 0.f, 0.f, 0.f);

    for (int it = 0; it < nIter; it++) {
        int p = beg + it * 4 + g;
        bool valid = (p < end);
        int pc = valid ? p : beg;          // nIter>0 implies beg<end
        int packed = d_csr[pc];
        int s = packed & 0xffff;
        int cat = packed >> 16;
        uint4 kk = *(const uint4*)(d_k16 + (size_t)s * 32 + fl * 4);
        uint4 vv = *(const uint4*)(d_v16 + (size_t)s * 32 + fl * 4);
        float2 kf0 = __half22float2(*(__half2*)&kk.x);
        float2 kf1 = __half22float2(*(__half2*)&kk.y);
        float2 kf2 = __half22float2(*(__half2*)&kk.z);
        float2 kf3 = __half22float2(*(__half2*)&kk.w);
        float dp = q0.x * kf0.x + q0.y * kf0.y + q0.z * kf1.x + q0.w * kf1.y +
                   q1.x * kf2.x + q1.y * kf2.y + q1.z * kf3.x + q1.w * kf3.y;
        dp += __shfl_xor_sync(0xffffffffu, dp, 1);
        dp += __shfl_xor_sync(0xffffffffu, dp, 2);
        dp += __shfl_xor_sync(0xffffffffu, dp, 4);
        float alpha = valid ? (dp + qe_s[wl][cat]) * SCALE : -1e30f;
        float w;
        if (alpha > m) {     // group-uniform branch
            float c = __expf(m - alpha);
            ssum *= c;
            acc0.x *= c; acc0.y *= c; acc0.z *= c; acc0.w *= c;
            acc1.x *= c; acc1.y *= c; acc1.z *= c; acc1.w *= c;
            m = alpha;
            w = 1.f;
        } else {
            w = __expf(alpha - m);
        }
        if (!valid) w = 0.f;
        ssum += w;
        float2 vf0 = __half22float2(*(__half2*)&vv.x);
        float2 vf1 = __half22float2(*(__half2*)&vv.y);
        float2 vf2 = __half22float2(*(__half2*)&vv.z);
        float2 vf3 = __half22float2(*(__half2*)&vv.w);
        const float* er = ec_s + cat * HH + fl * 8;
        float4 e0 = *(const float4*)er, e1 = *(const float4*)(er + 4);
        acc0.x += w * (vf0.x + e0.x);
        acc0.y += w * (vf0.y + e0.y);
        acc0.z += w * (vf1.x + e0.z);
        acc0.w += w * (vf1.y + e0.w);
        acc1.x += w * (vf2.x + e1.x);
        acc1.y += w * (vf2.y + e1.y);
        acc1.z += w * (vf3.x + e1.z);
        acc1.w += w * (vf3.y + e1.w);
    }

    // merge the 4 groups; afterwards every lane holds the merged state
#pragma unroll
    for (int o = 8; o <= 16; o <<= 1) {
        float mo = __shfl_xor_sync(0xffffffffu, m, o);
        float so = __shfl_xor_sync(0xffffffffu, ssum, o);
        float mn = fmaxf(m, mo);
        float cs = __expf(m - mn), co = __expf(mo - mn);
        ssum = ssum * cs + so * co;
        acc0.x = acc0.x * cs + __shfl_xor_sync(0xffffffffu, acc0.x, o) * co;
        acc0.y = acc0.y * cs + __shfl_xor_sync(0xffffffffu, acc0.y, o) * co;
        acc0.z = acc0.z * cs + __shfl_xor_sync(0xffffffffu, acc0.z, o) * co;
        acc0.w = acc0.w * cs + __shfl_xor_sync(0xffffffffu, acc0.w, o) * co;
        acc1.x = acc1.x * cs + __shfl_xor_sync(0xffffffffu, acc1.x, o) * co;
        acc1.y = acc1.y * cs + __shfl_xor_sync(0xffffffffu, acc1.y, o) * co;
        acc1.z = acc1.z * cs + __shfl_xor_sync(0xffffffffu, acc1.z, o) * co;
        acc1.w = acc1.w * cs + __shfl_xor_sync(0xffffffffu, acc1.w, o) * co;
        m = mn;
    }

    float inv = (ssum > 0.f) ? (1.f / ssum) : 0.f;
    const float* sr = d_s + (size_t)n * HH + fl * 8;
    float4 s0 = *(const float4*)sr, s1 = *(const float4*)(sr + 4);
    float4 h0, h1;
    h0.x = fmaxf(acc0.x * inv + s0.x, 0.f);
    h0.y = fmaxf(acc0.y * inv + s0.y, 0.f);
    h0.z = fmaxf(acc0.z * inv + s0.z, 0.f);
    h0.w = fmaxf(acc0.w * inv + s0.w, 0.f);
    h1.x = fmaxf(acc1.x * inv + s1.x, 0.f);
    h1.y = fmaxf(acc1.y * inv + s1.y, 0.f);
    h1.z = fmaxf(acc1.z * inv + s1.z, 0.f);
    h1.w = fmaxf(acc1.w * inv + s1.w, 0.f);
    if (g == 0) {
        *(float4*)(d_h + (size_t)n * HH + fl * 8) = h0;
        *(float4*)(d_h + (size_t)n * HH + fl * 8 + 4) = h1;
    }
    if (do_gate) {
        const float* gw = gate_W + fl * 8;
        float4 w0 = *(const float4*)gw, w1 = *(const float4*)(gw + 4);
        float gp = h0.x * w0.x + h0.y * w0.y + h0.z * w0.z + h0.w * w0.w +
                   h1.x * w1.x + h1.y * w1.y + h1.z * w1.z + h1.w * w1.w;
        gp += __shfl_xor_sync(0xffffffffu, gp, 1);
        gp += __shfl_xor_sync(0xffffffffu, gp, 2);
        gp += __shfl_xor_sync(0xffffffffu, gp, 4);
        if (lane == 0) {
            float gv = gp + gate_b[0];
            d_gate[n] = gv;
            atomicMax(&d_gmax[batch[n]], enc_f(gv));
        }
    }
}

// ---------------- readout -----------------------------------------------------

__global__ void gexp_kernel(const int* __restrict__ batch) {
    int n = blockIdx.x * blockDim.x + threadIdx.x;
    if (n >= NN) return;
    int b = batch[n];
    float g = __expf(d_gate[n] - dec_f(d_gmax[b]));
    d_gate[n] = g;
    atomicAdd(&d_gdenom[b], g);
}

__global__ void out_kernel(const int* __restrict__ batch,
                           const float* __restrict__ out_W,
                           const float* __restrict__ out_b,
                           float* __restrict__ out) {
    __shared__ float ow[HH * OUTD];   // 8KB
    __shared__ float hs[8][HH];
    int t = threadIdx.x;
    for (int i = t; i < HH * OUTD; i += 256) ow[i] = out_W[i];
    for (int i = t; i < 8 * HH; i += 256) {
        int r = i >> 6, c = i & 63;
        int n2 = blockIdx.x * 8 + r;
        hs[r][c] = (n2 < NN) ? d_h[n2 * HH + c] : 0.f;
    }
    __syncthreads();
    int j = t & 31, g = t >> 5;
    int n = blockIdx.x * 8 + g;
    if (n >= NN) return;
    float acc = out_b[j];
#pragma unroll
    for (int c = 0; c < HH; c++) acc += hs[g][c] * ow[c * OUTD + j];
    int b = batch[n];
    float w = d_gate[n] / d_gdenom[b];
    atomicAdd(&out[b * OUTD + j], w * acc);
}

// ---------------- launch -----------------------------------------------------

extern "C" void kernel_launch(void* const* d_in, const int* in_sizes, int n_in,
                              void* d_out, int out_size) {
    const int* x          = (const int*)d_in[0];
    const int* edge_index = (const int*)d_in[1];
    const int* src        = edge_index;
    const int* dst        = edge_index + EE;
    const int* ea         = (const int*)d_in[2];
    const int* batch      = (const int*)d_in[3];
    const float* node_emb = (const float*)d_in[4];
    const float* edge_emb = (const float*)d_in[5];
    const float* Wq       = (const float*)d_in[6];
    const float* Wk       = (const float*)d_in[7];
    const float* Wv       = (const float*)d_in[8];
    const float* We       = (const float*)d_in[9];
    const float* Wskip    = (const float*)d_in[10];
    const float* bq       = (const float*)d_in[11];
    const float* bk       = (const float*)d_in[12];
    const float* bv       = (const float*)d_in[13];
    const float* bskip    = (const float*)d_in[14];
    const float* gate_W   = (const float*)d_in[15];
    const float* gate_b   = (const float*)d_in[16];
    const float* out_W    = (const float*)d_in[17];
    const float* out_b    = (const float*)d_in[18];
    float* out            = (float*)d_out;

    const int N_BLOCKS  = (NN + 255) / 256;
    const int SCAN_BLOCKS = (NN + 1023) / 1024;   // 49: covers i <= NN

    // CSR build chain; d_deg is zero at entry (load-time zero + self-restore)
    hist_kernel<<<E_BLOCKS, 256>>>(dst);
    scan_blocks_kernel<<<SCAN_BLOCKS, 1024>>>();
    setup_kernel<<<64, 256>>>(out, edge_emb, We);   // bpre + ecat + readout init
    // scatter (needs bpre) runs CONCURRENTLY with proj layer 0 (needs nothing)
    scatter_proj0_kernel<<<PROJ_BLOCKS + E_BLOCKS, 256>>>(
        src, dst, ea,
        Wq, Wk, Wv, Wskip, bq, bk, bv, bskip, x, node_emb);

    dim3 gemm_grid(PROJ_BX, 4);
    const int ATTN_BLOCKS = (NN + 7) / 8;
    for (int l = 0; l < LL; l++) {
        if (l > 0) {
            proj_tc<<<gemm_grid, 256>>>(
                Wq + (size_t)l * HH * HH, Wk + (size_t)l * HH * HH,
                Wv + (size_t)l * HH * HH, Wskip + (size_t)l * HH * HH,
                bq + (size_t)l * HH, bk + (size_t)l * HH,
                bv + (size_t)l * HH, bskip + (size_t)l * HH,
                x, node_emb, 0);
        }
        attn_kernel<<<ATTN_BLOCKS, 256>>>(l, (l == LL - 1) ? 1 : 0,
                                          gate_W, gate_b, batch);
    }

    gexp_kernel<<<N_BLOCKS, 256>>>(batch);
    out_kernel<<<(NN + 7) / 8, 256>>>(batch, out_W, out_b, out);
}